// round 1
// baseline (speedup 1.0000x reference)
#include <cuda_runtime.h>
#include <math.h>

#define N_TOK 4096
#define DIM   1024
#define HID   768
#define NE    23
#define TOPK  3

#define BM 128
#define BN 64
#define BK 16

// ---------------- scratch (device globals; no allocs allowed) ----------------
__device__ float g_gw[(size_t)N_TOK * NE];            // normalized gate weights (for aux P)
__device__ int   g_counts[NE];                        // assignments per expert
__device__ int   g_list[(size_t)NE * N_TOK];          // per-expert slot list (slot = n*3+k)
__device__ float g_tw[(size_t)N_TOK * TOPK];          // per-slot routed weight
__device__ float g_Hs[(size_t)N_TOK * HID];           // shared-expert hidden
__device__ float g_Hr[(size_t)N_TOK * TOPK * HID];    // routed hidden, indexed by slot
__device__ float g_Yr[(size_t)N_TOK * TOPK * DIM];    // routed output, indexed by slot

__device__ __forceinline__ float gelu_exact(float v) {
    return 0.5f * v * (1.0f + erff(v * 0.7071067811865476f));
}

// ---------------- init: zero per-expert counters ----------------
__global__ void init_kernel() {
    int t = threadIdx.x;
    if (t < NE) g_counts[t] = 0;
}

// ---------------- gate: sigmoid gate, top-3, routing lists ----------------
__global__ void gate_kernel(const float* __restrict__ x,
                            const float* __restrict__ gW,
                            const float* __restrict__ gb,
                            const float* __restrict__ rbias)
{
    __shared__ float xs[DIM];
    __shared__ float gv[NE];
    __shared__ float gsum_s;
    int n = blockIdx.x;
    int t = threadIdx.x;

    const float4* xv  = (const float4*)(x + (size_t)n * DIM);
    float4*       xsv = (float4*)xs;
    for (int i = t; i < DIM / 4; i += 128) xsv[i] = xv[i];
    __syncthreads();

    int e = t >> 2, j = t & 3;
    float acc = 0.f;
    if (e < NE) {
        for (int i = j; i < DIM; i += 4)
            acc += xs[i] * gW[i * NE + e];
    }
    acc += __shfl_xor_sync(0xffffffffu, acc, 1);
    acc += __shfl_xor_sync(0xffffffffu, acc, 2);
    if (e < NE && j == 0)
        gv[e] = 1.0f / (1.0f + expf(-(acc + gb[e])));
    __syncthreads();

    if (t == 0) {
        float s = 0.f;
        for (int q = 0; q < NE; q++) s += gv[q];
        gsum_s = s;
    }
    __syncthreads();

    if (t < NE) g_gw[(size_t)n * NE + t] = gv[t] / gsum_s;

    if (t == 0) {
        int   idx[TOPK];
        float w[TOPK];
        unsigned used = 0;
        for (int k = 0; k < TOPK; k++) {
            float best = -1e30f; int bi = 0;
            for (int q = 0; q < NE; q++) {
                if (used & (1u << q)) continue;
                float s = gv[q] + rbias[q];
                if (s > best) { best = s; bi = q; }  // strict > keeps lowest index on ties
            }
            used |= (1u << bi);
            idx[k] = bi;
            w[k]   = gv[bi];
        }
        float ws = w[0] + w[1] + w[2];
        for (int k = 0; k < TOPK; k++) {
            int slot = n * TOPK + k;
            g_tw[slot] = w[k] / ws;
            int pos = atomicAdd(&g_counts[idx[k]], 1);
            g_list[(size_t)idx[k] * N_TOK + pos] = slot;
        }
    }
}

// ---------------- aux loss (deterministic tree reduction) ----------------
__global__ void aux_kernel(float* __restrict__ out, int out_size)
{
    __shared__ float sm[256 * NE];
    int t = threadIdx.x;
    float loc[NE];
    #pragma unroll
    for (int e = 0; e < NE; e++) loc[e] = 0.f;
    for (int n = t; n < N_TOK; n += 256) {
        #pragma unroll
        for (int e = 0; e < NE; e++) loc[e] += g_gw[(size_t)n * NE + e];
    }
    for (int e = 0; e < NE; e++) sm[t * NE + e] = loc[e];
    __syncthreads();
    for (int s = 128; s > 0; s >>= 1) {
        if (t < s)
            for (int e = 0; e < NE; e++) sm[t * NE + e] += sm[(t + s) * NE + e];
        __syncthreads();
    }
    if (t == 0 && out_size > N_TOK * DIM) {
        float aux = 0.f;
        for (int e = 0; e < NE; e++) {
            float P = sm[e] / (float)N_TOK;
            float F = ((float)NE * (float)g_counts[e]) / ((float)TOPK * (float)N_TOK);
            aux += P * F;
        }
        out[(size_t)N_TOK * DIM] = aux;
    }
}

// ---------------- tiled GEMM: covers all 4 MLP launches ----------------
// MLP1:  Out[row] = gelu(A_gather @ W + bias), KDIM=DIM, NOUT=HID
// MLP2:  Out[row] = (A_gather @ W + bias) [* g_tw[slot] if routed], KDIM=HID, NOUT=DIM
template<int KDIM, int NOUT, bool ROUTED, bool MLP1>
__global__ void __launch_bounds__(256, 2) mlp_kernel(
    const float* __restrict__ A,
    const float* __restrict__ Wb,
    const float* __restrict__ Bb,
    float* __restrict__ Out)
{
    int e   = blockIdx.z;
    int cnt = ROUTED ? g_counts[e] : N_TOK;
    int m0  = blockIdx.x * BM;
    if (m0 >= cnt) return;
    int n0  = blockIdx.y * BN;

    const float* W    = Wb + (ROUTED ? (size_t)e * KDIM * NOUT : 0);
    const float* bias = Bb + (ROUTED ? (size_t)e * NOUT : 0);

    __shared__ float As[BK][BM];
    __shared__ float Bs[BK][BN];

    int tid = threadIdx.x;
    int tx = tid & 15, ty = tid >> 4;

    // A loader: rows (tid>>2) and +64, 4 cols at (tid&3)*4
    int lr = tid >> 2;
    int lc = (tid & 3) * 4;
    int gi0 = m0 + lr, gi1 = m0 + lr + 64;
    int ar0, ar1;
    if (ROUTED) {
        int s0 = (gi0 < cnt) ? g_list[(size_t)e * N_TOK + gi0] : 0;
        int s1 = (gi1 < cnt) ? g_list[(size_t)e * N_TOK + gi1] : 0;
        ar0 = MLP1 ? (s0 / TOPK) : s0;   // MLP1 gathers x by token; MLP2 gathers Hr by slot
        ar1 = MLP1 ? (s1 / TOPK) : s1;
    } else { ar0 = gi0; ar1 = gi1; }
    const float* Ap0 = A + (size_t)ar0 * KDIM + lc;
    const float* Ap1 = A + (size_t)ar1 * KDIM + lc;

    // B loader: row tid>>4 (0..15), 4 cols at (tid&15)*4
    int br = tid >> 4;
    int bc = (tid & 15) * 4;
    const float* Bp = W + (size_t)br * NOUT + n0 + bc;

    float acc[8][4];
    #pragma unroll
    for (int r = 0; r < 8; r++)
        #pragma unroll
        for (int c = 0; c < 4; c++) acc[r][c] = 0.f;

    // register prefetch of first tile
    float4 a0 = *(const float4*)(Ap0);
    float4 a1 = *(const float4*)(Ap1);
    float4 b  = *(const float4*)(Bp);

    for (int k0 = 0; k0 < KDIM; k0 += BK) {
        __syncthreads();
        As[lc + 0][lr] = a0.x; As[lc + 1][lr] = a0.y;
        As[lc + 2][lr] = a0.z; As[lc + 3][lr] = a0.w;
        As[lc + 0][lr + 64] = a1.x; As[lc + 1][lr + 64] = a1.y;
        As[lc + 2][lr + 64] = a1.z; As[lc + 3][lr + 64] = a1.w;
        *(float4*)&Bs[br][bc] = b;
        __syncthreads();

        if (k0 + BK < KDIM) {  // prefetch next tile while computing
            a0 = *(const float4*)(Ap0 + k0 + BK);
            a1 = *(const float4*)(Ap1 + k0 + BK);
            b  = *(const float4*)(Bp + (size_t)(k0 + BK) * NOUT);
        }

        #pragma unroll
        for (int kk = 0; kk < BK; kk++) {
            float4 av0 = *(const float4*)&As[kk][ty * 8];
            float4 av1 = *(const float4*)&As[kk][ty * 8 + 4];
            float4 bv  = *(const float4*)&Bs[kk][tx * 4];
            float ar[8] = {av0.x, av0.y, av0.z, av0.w, av1.x, av1.y, av1.z, av1.w};
            float bb[4] = {bv.x, bv.y, bv.z, bv.w};
            #pragma unroll
            for (int r = 0; r < 8; r++)
                #pragma unroll
                for (int c = 0; c < 4; c++)
                    acc[r][c] += ar[r] * bb[c];
        }
    }

    // epilogue
    int col = n0 + tx * 4;
    float4 bb4 = *(const float4*)(bias + col);
    #pragma unroll
    for (int r = 0; r < 8; r++) {
        int i = m0 + ty * 8 + r;
        if (i < cnt) {
            float4 v;
            v.x = acc[r][0] + bb4.x;
            v.y = acc[r][1] + bb4.y;
            v.z = acc[r][2] + bb4.z;
            v.w = acc[r][3] + bb4.w;
            size_t orow;
            if (ROUTED) {
                int slot = g_list[(size_t)e * N_TOK + i];
                orow = (size_t)slot;
                if (!MLP1) {
                    float wgt = g_tw[slot];
                    v.x *= wgt; v.y *= wgt; v.z *= wgt; v.w *= wgt;
                }
            } else {
                orow = (size_t)i;
            }
            if (MLP1) {
                v.x = gelu_exact(v.x); v.y = gelu_exact(v.y);
                v.z = gelu_exact(v.z); v.w = gelu_exact(v.w);
            }
            *(float4*)(Out + orow * NOUT + col) = v;
        }
    }
}

// ---------------- combine: out += sum_k Yr[slot] (deterministic, no atomics) ----------------
__global__ void combine_kernel(float* __restrict__ out)
{
    int idx = blockIdx.x * blockDim.x + threadIdx.x;  // over N_TOK*DIM/4 float4s
    if (idx >= N_TOK * (DIM / 4)) return;
    int n  = idx / (DIM / 4);
    int d4 = idx % (DIM / 4);
    float4 v = ((float4*)out)[idx];
    const float4* yr = (const float4*)g_Yr;
    #pragma unroll
    for (int k = 0; k < TOPK; k++) {
        float4 y = yr[(size_t)(n * TOPK + k) * (DIM / 4) + d4];
        v.x += y.x; v.y += y.y; v.z += y.z; v.w += y.w;
    }
    ((float4*)out)[idx] = v;
}

// ---------------- launch ----------------
extern "C" void kernel_launch(void* const* d_in, const int* in_sizes, int n_in,
                              void* d_out, int out_size)
{
    const float* x   = (const float*)d_in[0];
    const float* gW  = (const float*)d_in[1];
    const float* gb  = (const float*)d_in[2];
    const float* rb  = (const float*)d_in[3];
    const float* W1  = (const float*)d_in[4];
    const float* b1  = (const float*)d_in[5];
    const float* W2  = (const float*)d_in[6];
    const float* b2  = (const float*)d_in[7];
    const float* sW1 = (const float*)d_in[8];
    const float* sb1 = (const float*)d_in[9];
    const float* sW2 = (const float*)d_in[10];
    const float* sb2 = (const float*)d_in[11];
    float* out = (float*)d_out;

    void* p;
    cudaGetSymbolAddress(&p, g_Hs); float* Hs = (float*)p;
    cudaGetSymbolAddress(&p, g_Hr); float* Hr = (float*)p;
    cudaGetSymbolAddress(&p, g_Yr); float* Yr = (float*)p;

    init_kernel<<<1, 32>>>();
    gate_kernel<<<N_TOK, 128>>>(x, gW, gb, rb);
    aux_kernel<<<1, 256>>>(out, out_size);

    // shared MLP1: [4096,1024] @ [1024,768] -> gelu -> Hs
    mlp_kernel<DIM, HID, false, true ><<<dim3(N_TOK / BM, HID / BN, 1),  256>>>(x,  sW1, sb1, Hs);
    // routed MLP1: gathered x @ W1[e] -> gelu -> Hr (slot-indexed)
    mlp_kernel<DIM, HID, true,  true ><<<dim3(N_TOK / BM, HID / BN, NE), 256>>>(x,  W1,  b1,  Hr);
    // shared MLP2: Hs @ [768,1024] -> out (base)
    mlp_kernel<HID, DIM, false, false><<<dim3(N_TOK / BM, DIM / BN, 1),  256>>>(Hs, sW2, sb2, out);
    // routed MLP2: Hr @ W2[e] -> weighted -> Yr (slot-indexed)
    mlp_kernel<HID, DIM, true,  false><<<dim3(N_TOK / BM, DIM / BN, NE), 256>>>(Hr, W2,  b2,  Yr);

    combine_kernel<<<(N_TOK * (DIM / 4) + 255) / 256, 256>>>(out);
}

// round 3
// speedup vs baseline: 1.6596x; 1.6596x over previous
#include <cuda_runtime.h>
#include <cuda_bf16.h>
#include <math.h>
#include <stdint.h>

#define N_TOK 4096
#define DIM   1024
#define HID   768
#define NE    23
#define TOPK  3
#define NSLOT (N_TOK * TOPK)

// GEMM tiling
#define TBM 128
#define TBN 128
#define TBK 32
// smem layout (bytes, per stage): A rows padded to 80B, B rows padded to 272B
#define A_STRIDE 80
#define B_STRIDE 272
#define AH_OFF 0
#define AL_OFF 10240
#define BH_OFF 20480
#define BL_OFF 29184
#define STG    37888
#define SMEM_SZ (2 * STG)   // 75776; epilogue (128*132*4=67584) reuses it

// ---------------- scratch ----------------
__device__ float g_gw[(size_t)N_TOK * NE];
__device__ int   g_counts[NE];
__device__ int   g_list[(size_t)NE * N_TOK];
__device__ float g_tw[NSLOT];
__device__ float g_Hs[(size_t)N_TOK * HID];
__device__ float g_Hr[(size_t)NSLOT * HID];
__device__ float g_Yr[(size_t)NSLOT * DIM];

__device__ __forceinline__ float gelu_exact(float v) {
    return 0.5f * v * (1.0f + erff(v * 0.7071067811865476f));
}

__device__ __forceinline__ uint32_t smem_u32(const void* p) {
    uint32_t a;
    asm("{ .reg .u64 t; cvta.to.shared.u64 t, %1; cvt.u32.u64 %0, t; }" : "=r"(a) : "l"(p));
    return a;
}
__device__ __forceinline__ void ldsm_x4(uint32_t addr, uint32_t* r) {
    asm volatile("ldmatrix.sync.aligned.m8n8.x4.shared.b16 {%0,%1,%2,%3}, [%4];"
                 : "=r"(r[0]), "=r"(r[1]), "=r"(r[2]), "=r"(r[3]) : "r"(addr));
}
__device__ __forceinline__ void ldsm_x4_t(uint32_t addr, uint32_t* r) {
    asm volatile("ldmatrix.sync.aligned.m8n8.x4.trans.shared.b16 {%0,%1,%2,%3}, [%4];"
                 : "=r"(r[0]), "=r"(r[1]), "=r"(r[2]), "=r"(r[3]) : "r"(addr));
}
__device__ __forceinline__ void mma_bf16(float* c, const uint32_t* a, uint32_t b0, uint32_t b1) {
    asm volatile("mma.sync.aligned.m16n8k16.row.col.f32.bf16.bf16.f32 "
                 "{%0,%1,%2,%3}, {%4,%5,%6,%7}, {%8,%9}, {%0,%1,%2,%3};"
                 : "+f"(c[0]), "+f"(c[1]), "+f"(c[2]), "+f"(c[3])
                 : "r"(a[0]), "r"(a[1]), "r"(a[2]), "r"(a[3]), "r"(b0), "r"(b1));
}

__device__ __forceinline__ uint32_t pack2(__nv_bfloat16 a, __nv_bfloat16 b) {
    return (uint32_t)__bfloat16_as_ushort(a) | ((uint32_t)__bfloat16_as_ushort(b) << 16);
}
// split float4 into hi/lo bf16 packed uint2s
__device__ __forceinline__ void split4(float4 v, uint2& h, uint2& l) {
    float vv[4] = {v.x, v.y, v.z, v.w};
    __nv_bfloat16 hh[4], ll[4];
    #pragma unroll
    for (int q = 0; q < 4; q++) {
        hh[q] = __float2bfloat16(vv[q]);
        ll[q] = __float2bfloat16(vv[q] - __bfloat162float(hh[q]));
    }
    h = make_uint2(pack2(hh[0], hh[1]), pack2(hh[2], hh[3]));
    l = make_uint2(pack2(ll[0], ll[1]), pack2(ll[2], ll[3]));
}

// ---------------- init ----------------
__global__ void init_kernel() {
    int t = threadIdx.x;
    if (t < NE) g_counts[t] = 0;
}

// ---------------- gate (known-correct from R1) ----------------
__global__ void gate_kernel(const float* __restrict__ x,
                            const float* __restrict__ gW,
                            const float* __restrict__ gb,
                            const float* __restrict__ rbias)
{
    __shared__ float xs[DIM];
    __shared__ float gv[NE];
    __shared__ float gsum_s;
    int n = blockIdx.x;
    int t = threadIdx.x;

    const float4* xv  = (const float4*)(x + (size_t)n * DIM);
    float4*       xsv = (float4*)xs;
    for (int i = t; i < DIM / 4; i += 128) xsv[i] = xv[i];
    __syncthreads();

    int e = t >> 2, j = t & 3;
    float acc = 0.f;
    if (e < NE) {
        for (int i = j; i < DIM; i += 4)
            acc += xs[i] * gW[i * NE + e];
    }
    acc += __shfl_xor_sync(0xffffffffu, acc, 1);
    acc += __shfl_xor_sync(0xffffffffu, acc, 2);
    if (e < NE && j == 0)
        gv[e] = 1.0f / (1.0f + expf(-(acc + gb[e])));
    __syncthreads();

    if (t == 0) {
        float s = 0.f;
        for (int q = 0; q < NE; q++) s += gv[q];
        gsum_s = s;
    }
    __syncthreads();

    if (t < NE) g_gw[(size_t)n * NE + t] = gv[t] / gsum_s;

    if (t == 0) {
        int   idx[TOPK];
        float w[TOPK];
        unsigned used = 0;
        for (int k = 0; k < TOPK; k++) {
            float best = -1e30f; int bi = 0;
            for (int q = 0; q < NE; q++) {
                if (used & (1u << q)) continue;
                float s = gv[q] + rbias[q];
                if (s > best) { best = s; bi = q; }
            }
            used |= (1u << bi);
            idx[k] = bi;
            w[k]   = gv[bi];
        }
        float ws = w[0] + w[1] + w[2];
        for (int k = 0; k < TOPK; k++) {
            int slot = n * TOPK + k;
            g_tw[slot] = w[k] / ws;
            int pos = atomicAdd(&g_counts[idx[k]], 1);
            g_list[(size_t)idx[k] * N_TOK + pos] = slot;
        }
    }
}

// ---------------- aux loss ----------------
__global__ void aux_kernel(float* __restrict__ out, int out_size)
{
    __shared__ float sm[256 * NE];
    int t = threadIdx.x;
    float loc[NE];
    #pragma unroll
    for (int e = 0; e < NE; e++) loc[e] = 0.f;
    for (int n = t; n < N_TOK; n += 256) {
        #pragma unroll
        for (int e = 0; e < NE; e++) loc[e] += g_gw[(size_t)n * NE + e];
    }
    for (int e = 0; e < NE; e++) sm[t * NE + e] = loc[e];
    __syncthreads();
    for (int s = 128; s > 0; s >>= 1) {
        if (t < s)
            for (int e = 0; e < NE; e++) sm[t * NE + e] += sm[(t + s) * NE + e];
        __syncthreads();
    }
    if (t == 0 && out_size > N_TOK * DIM) {
        float aux = 0.f;
        for (int e = 0; e < NE; e++) {
            float P = sm[e] / (float)N_TOK;
            float F = ((float)NE * (float)g_counts[e]) / ((float)TOPK * (float)N_TOK);
            aux += P * F;
        }
        out[(size_t)N_TOK * DIM] = aux;
    }
}

// ---------------- bf16 3-term split GEMM via mma.sync ----------------
// D[m][n] = sum_k A[m][k]*B[k][n] (fp32 inputs, split to bf16 hi/lo in loader)
// MLP1: Out[row] = gelu(D + bias) fp32;  MLP2: Out[row] = (D + bias)[*tw]
template<int KDIM, int NOUT, bool ROUTED, bool MLP1>
__global__ void __launch_bounds__(256, 1) mma_mlp(
    const float* __restrict__ A,
    const float* __restrict__ Bg,
    const float* __restrict__ BiasAll,
    float* __restrict__ OutF)
{
    constexpr int NC = KDIM / TBK;

    int e   = blockIdx.z;
    int cnt = ROUTED ? g_counts[e] : N_TOK;
    int m0  = blockIdx.x * TBM;
    if (m0 >= cnt) return;
    int n0  = blockIdx.y * TBN;

    extern __shared__ char smem[];
    uint32_t sbase = smem_u32(smem);

    int tid  = threadIdx.x;
    int wid  = tid >> 5;
    int lane = tid & 31;
    int wm   = wid >> 2;   // 0..1 : rows wm*64..+63
    int wn   = wid & 3;    // 0..3 : cols wn*32..+31

    const float* Bgz  = Bg + (ROUTED ? (size_t)e * KDIM * NOUT : 0);
    const float* bias = BiasAll + (ROUTED ? (size_t)e * NOUT : 0);

    // ---- loader setup ----
    // A: thread t handles row t>>1, k-half t&1 (16 floats = 4 float4)
    int arow = tid >> 1;
    int ah   = tid & 1;
    int gi_a = m0 + arow;
    int grow;
    if (ROUTED) {
        int gg   = (gi_a < cnt) ? gi_a : (cnt - 1);
        int slot = g_list[(size_t)e * N_TOK + gg];
        grow = MLP1 ? (slot / TOPK) : slot;
    } else {
        grow = gi_a;
    }
    const float* Aptr = A + (size_t)grow * KDIM + ah * 16;
    uint32_t aoff = (uint32_t)(arow * A_STRIDE + ah * 32);

    // B: thread t handles k-row t>>3, col group t&7 (4 float4 strided by 32 floats)
    int bk = tid >> 3;
    int bc = tid & 7;
    const float* Bptr = Bgz + (size_t)bk * NOUT + n0 + bc * 4;
    uint32_t boff = (uint32_t)(bk * B_STRIDE + bc * 8);

    float4 fa[4], fb[4];
    #pragma unroll
    for (int q = 0; q < 4; q++) {
        fa[q] = *(const float4*)(Aptr + q * 4);
        fb[q] = *(const float4*)(Bptr + q * 32);
    }

    // store chunk 0 into stage 0
    {
        char* st = smem;
        #pragma unroll
        for (int q = 0; q < 4; q++) {
            uint2 h, l;
            split4(fa[q], h, l);
            *(uint2*)(st + AH_OFF + aoff + q * 8) = h;
            *(uint2*)(st + AL_OFF + aoff + q * 8) = l;
            split4(fb[q], h, l);
            *(uint2*)(st + BH_OFF + boff + q * 64) = h;
            *(uint2*)(st + BL_OFF + boff + q * 64) = l;
        }
    }
    __syncthreads();

    float acc[4][4][4];
    #pragma unroll
    for (int i = 0; i < 4; i++)
        #pragma unroll
        for (int j = 0; j < 4; j++)
            #pragma unroll
            for (int q = 0; q < 4; q++) acc[i][j][q] = 0.f;

    // fragment base addresses (stage 0)
    uint32_t aAddr = sbase + AH_OFF + (uint32_t)((wm * 64 + (lane & 15)) * A_STRIDE + ((lane >> 4) << 4));
    uint32_t bAddr = sbase + BH_OFF + (uint32_t)((lane & 15) * B_STRIDE + ((wn * 32 + (lane >> 4) * 8) << 1));

    for (int c = 0; c < NC; c++) {
        int s = c & 1;
        // prefetch next chunk from global
        if (c + 1 < NC) {
            int k0 = (c + 1) * TBK;
            #pragma unroll
            for (int q = 0; q < 4; q++) {
                fa[q] = *(const float4*)(Aptr + k0 + q * 4);
                fb[q] = *(const float4*)(Bptr + (size_t)k0 * NOUT + q * 32);
            }
        }
        // compute from stage s
        uint32_t aS = aAddr + (uint32_t)(s * STG);
        uint32_t bS = bAddr + (uint32_t)(s * STG);
        #pragma unroll
        for (int ks = 0; ks < 2; ks++) {
            uint32_t ahF[4][4], alF[4][4];
            #pragma unroll
            for (int i = 0; i < 4; i++) {
                ldsm_x4(aS + ks * 32 + i * (16 * A_STRIDE), ahF[i]);
                ldsm_x4(aS + ks * 32 + i * (16 * A_STRIDE) + (AL_OFF - AH_OFF), alF[i]);
            }
            uint32_t bhF[2][4], blF[2][4];
            #pragma unroll
            for (int g = 0; g < 2; g++) {
                ldsm_x4_t(bS + ks * (16 * B_STRIDE) + g * 32, bhF[g]);
                ldsm_x4_t(bS + ks * (16 * B_STRIDE) + g * 32 + (BL_OFF - BH_OFF), blF[g]);
            }
            #pragma unroll
            for (int i = 0; i < 4; i++) {
                #pragma unroll
                for (int j = 0; j < 4; j++) {
                    int g = j >> 1, o = (j & 1) * 2;
                    mma_bf16(acc[i][j], ahF[i], bhF[g][o], bhF[g][o + 1]);
                    mma_bf16(acc[i][j], ahF[i], blF[g][o], blF[g][o + 1]);
                    mma_bf16(acc[i][j], alF[i], bhF[g][o], bhF[g][o + 1]);
                }
            }
        }
        __syncthreads();
        // store prefetched chunk into other stage
        if (c + 1 < NC) {
            char* st = smem + (s ^ 1) * STG;
            #pragma unroll
            for (int q = 0; q < 4; q++) {
                uint2 h, l;
                split4(fa[q], h, l);
                *(uint2*)(st + AH_OFF + aoff + q * 8) = h;
                *(uint2*)(st + AL_OFF + aoff + q * 8) = l;
                split4(fb[q], h, l);
                *(uint2*)(st + BH_OFF + boff + q * 64) = h;
                *(uint2*)(st + BL_OFF + boff + q * 64) = l;
            }
            __syncthreads();
        }
    }

    // ---- epilogue: frags -> smem (128 x 132 fp32), then coalesced global ----
    float* epi = (float*)smem;
    {
        int rb = wm * 64 + (lane >> 2);
        int cb = wn * 32 + (lane & 3) * 2;
        #pragma unroll
        for (int i = 0; i < 4; i++) {
            #pragma unroll
            for (int j = 0; j < 4; j++) {
                int r = rb + i * 16;
                int cc = cb + j * 8;
                epi[r * 132 + cc]           = acc[i][j][0];
                epi[r * 132 + cc + 1]       = acc[i][j][1];
                epi[(r + 8) * 132 + cc]     = acc[i][j][2];
                epi[(r + 8) * 132 + cc + 1] = acc[i][j][3];
            }
        }
    }
    __syncthreads();

    for (int i = tid; i < TBM * (TBN / 4); i += 256) {
        int r  = i >> 5;
        int c4 = i & 31;
        int gi = m0 + r;
        if (ROUTED && gi >= cnt) continue;
        float4 v = *(float4*)&epi[r * 132 + c4 * 4];
        int col = n0 + c4 * 4;
        float4 b4 = *(const float4*)(bias + col);
        v.x += b4.x; v.y += b4.y; v.z += b4.z; v.w += b4.w;
        size_t orow;
        if (ROUTED) {
            int slot = g_list[(size_t)e * N_TOK + gi];
            orow = (size_t)slot;
            if (!MLP1) {
                float w = g_tw[slot];
                v.x *= w; v.y *= w; v.z *= w; v.w *= w;
            }
        } else {
            orow = (size_t)gi;
        }
        if (MLP1) {
            v.x = gelu_exact(v.x); v.y = gelu_exact(v.y);
            v.z = gelu_exact(v.z); v.w = gelu_exact(v.w);
        }
        *(float4*)(OutF + orow * NOUT + col) = v;
    }
}

// ---------------- combine ----------------
__global__ void combine_kernel(float* __restrict__ out)
{
    int idx = blockIdx.x * blockDim.x + threadIdx.x;
    if (idx >= N_TOK * (DIM / 4)) return;
    int n  = idx / (DIM / 4);
    int d4 = idx % (DIM / 4);
    float4 v = ((float4*)out)[idx];
    const float4* yr = (const float4*)g_Yr;
    #pragma unroll
    for (int k = 0; k < TOPK; k++) {
        float4 y = yr[(size_t)(n * TOPK + k) * (DIM / 4) + d4];
        v.x += y.x; v.y += y.y; v.z += y.z; v.w += y.w;
    }
    ((float4*)out)[idx] = v;
}

// ---------------- launch ----------------
extern "C" void kernel_launch(void* const* d_in, const int* in_sizes, int n_in,
                              void* d_out, int out_size)
{
    const float* x   = (const float*)d_in[0];
    const float* gW  = (const float*)d_in[1];
    const float* gb  = (const float*)d_in[2];
    const float* rb  = (const float*)d_in[3];
    const float* W1  = (const float*)d_in[4];
    const float* b1  = (const float*)d_in[5];
    const float* W2  = (const float*)d_in[6];
    const float* b2  = (const float*)d_in[7];
    const float* sW1 = (const float*)d_in[8];
    const float* sb1 = (const float*)d_in[9];
    const float* sW2 = (const float*)d_in[10];
    const float* sb2 = (const float*)d_in[11];
    float* out = (float*)d_out;

    void* p;
    cudaGetSymbolAddress(&p, g_Hs); float* Hs = (float*)p;
    cudaGetSymbolAddress(&p, g_Hr); float* Hr = (float*)p;
    cudaGetSymbolAddress(&p, g_Yr); float* Yr = (float*)p;

    cudaFuncSetAttribute(mma_mlp<DIM, HID, false, true >, cudaFuncAttributeMaxDynamicSharedMemorySize, SMEM_SZ);
    cudaFuncSetAttribute(mma_mlp<DIM, HID, true , true >, cudaFuncAttributeMaxDynamicSharedMemorySize, SMEM_SZ);
    cudaFuncSetAttribute(mma_mlp<HID, DIM, false, false>, cudaFuncAttributeMaxDynamicSharedMemorySize, SMEM_SZ);
    cudaFuncSetAttribute(mma_mlp<HID, DIM, true , false>, cudaFuncAttributeMaxDynamicSharedMemorySize, SMEM_SZ);

    init_kernel<<<1, 32>>>();
    gate_kernel<<<N_TOK, 128>>>(x, gW, gb, rb);
    aux_kernel<<<1, 256>>>(out, out_size);

    // shared MLP1: x @ sW1 -> gelu -> Hs
    mma_mlp<DIM, HID, false, true ><<<dim3(N_TOK / TBM, HID / TBN, 1 ), 256, SMEM_SZ>>>(x,  sW1, sb1, Hs);
    // routed MLP1: gather(x) @ W1[e] -> gelu -> Hr (slot rows)
    mma_mlp<DIM, HID, true , true ><<<dim3(N_TOK / TBM, HID / TBN, NE), 256, SMEM_SZ>>>(x,  W1,  b1,  Hr);
    // shared MLP2: Hs @ sW2 -> out
    mma_mlp<HID, DIM, false, false><<<dim3(N_TOK / TBM, DIM / TBN, 1 ), 256, SMEM_SZ>>>(Hs, sW2, sb2, out);
    // routed MLP2: Hr @ W2[e] -> *tw -> Yr (slot rows)
    mma_mlp<HID, DIM, true , false><<<dim3(N_TOK / TBM, DIM / TBN, NE), 256, SMEM_SZ>>>(Hr, W2,  b2,  Yr);

    combine_kernel<<<(N_TOK * (DIM / 4) + 255) / 256, 256>>>(out);
}